// round 8
// baseline (speedup 1.0000x reference)
#include <cuda_runtime.h>
#include <cuda_bf16.h>
#include <math.h>
#include <stdint.h>

#define NN 50000          // nodes
#define NE 400000         // input edges
#define ET 450000         // edges + self loops
#define H0 8
#define C0 64
#define F0 128
#define FH 512            // H0*C0
#define NC 16

// ---------------- device scratch (no allocations allowed) ----------------
__device__ float g_bufA[NN * FH];      // linear GEMM output per layer
__device__ float g_bufB[NN * FH];      // aggregated+activated output
__device__ float g_bufC[NN * NC];      // layer-2 linear output
__device__ float g_als[NN * H0];
__device__ float g_ald[NN * H0];
__device__ float g_ex [ET * H0];       // per-(edge,head) alpha staging
__device__ int   g_deg[NN];
__device__ int   g_rowptr[NN + 1];
__device__ int   g_cursor[NN];
__device__ int   g_csr[ET];            // src node per CSR slot (sorted by dst)

__device__ __forceinline__ int clampi(int v) {
    return v < 0 ? 0 : (v >= NN ? NN - 1 : v);
}

// ---------------- CSR construction (edge_index is INT32: [2, NE]) ----------------
__global__ void k_zero_deg() {
    int i = blockIdx.x * blockDim.x + threadIdx.x;
    if (i < NN) g_deg[i] = 0;
}

__global__ void k_hist(const int* __restrict__ ei) {
    int e = blockIdx.x * blockDim.x + threadIdx.x;
    if (e >= ET) return;
    int d;
    if (e < NE) d = clampi(ei[NE + e]);
    else        d = e - NE;           // self loop
    atomicAdd(&g_deg[d], 1);
}

__global__ void k_scan() {           // single block, 1024 threads, exclusive scan
    __shared__ int s[1024];
    __shared__ int carry;
    int tid = threadIdx.x;
    if (tid == 0) carry = 0;
    __syncthreads();
    for (int base = 0; base < NN; base += 1024) {
        int i = base + tid;
        int v = (i < NN) ? g_deg[i] : 0;
        s[tid] = v;
        __syncthreads();
        for (int off = 1; off < 1024; off <<= 1) {
            int t = (tid >= off) ? s[tid - off] : 0;
            __syncthreads();
            s[tid] += t;
            __syncthreads();
        }
        if (i < NN) {
            int excl = carry + s[tid] - v;
            g_rowptr[i] = excl;
            g_cursor[i] = excl;
        }
        int tot = s[1023];
        __syncthreads();
        if (tid == 0) carry += tot;
        __syncthreads();
    }
    if (tid == 0) g_rowptr[NN] = ET;
}

__global__ void k_scatter(const int* __restrict__ ei) {
    int e = blockIdx.x * blockDim.x + threadIdx.x;
    if (e >= ET) return;
    int srcv, d;
    if (e < NE) { srcv = clampi(ei[e]); d = clampi(ei[NE + e]); }
    else        { srcv = e - NE;        d = e - NE; }
    int p = atomicAdd(&g_cursor[d], 1);
    if (p >= 0 && p < ET) g_csr[p] = srcv;
}

// ================= mma.sync tf32 GEMM (3xTF32 split): C = A(MxK)*W(KxN) =================
__device__ __forceinline__ uint32_t tf32_rna(float f) {
    uint32_t r;
    asm("cvt.rna.tf32.f32 %0, %1;" : "=r"(r) : "f"(f));
    return r;
}
#define MMA_TF32(d, a, b) \
    asm volatile("mma.sync.aligned.m16n8k8.row.col.f32.tf32.tf32.f32 " \
        "{%0,%1,%2,%3}, {%4,%5,%6,%7}, {%8,%9}, {%0,%1,%2,%3};" \
        : "+f"((d)[0]), "+f"((d)[1]), "+f"((d)[2]), "+f"((d)[3]) \
        : "r"((a)[0]), "r"((a)[1]), "r"((a)[2]), "r"((a)[3]), \
          "r"((b)[0]), "r"((b)[1]))

#define APAD 36              // A smem row stride (floats): (4m+k)%32 distinct -> conflict-free
#define BPAD 136             // B smem row stride (floats): (8k+n)%32 distinct -> conflict-free
#define SM_AH 0
#define SM_AL (128 * APAD)
#define SM_BH (2 * 128 * APAD)
#define SM_BL (SM_BH + 32 * BPAD)
#define MMASM ((2 * 128 * APAD + 2 * 32 * BPAD) * 4)   // 71680 bytes

// ASEL: -1 = Aext param, 1 = g_bufB.  C = g_bufA.  Requires K%32==0, N%128==0.
template <int ASEL>
__global__ void __launch_bounds__(256, 1)
mma_gemm(const float* __restrict__ Aext, const float* __restrict__ W, int M, int N, int K) {
    const float* __restrict__ A = (ASEL == 1) ? (const float*)g_bufB : Aext;
    float* __restrict__ C = g_bufA;

    extern __shared__ uint32_t sm[];

    const int tid = threadIdx.x;
    const int lane = tid & 31;
    const int wid = tid >> 5;
    const int wm = (wid & 1) * 64;      // warp M offset in block tile
    const int wn = (wid >> 1) * 32;     // warp N offset
    const int row0 = blockIdx.y * 128;
    const int col0 = blockIdx.x * 128;

    float c[4][4][4];
#pragma unroll
    for (int mt = 0; mt < 4; mt++)
#pragma unroll
        for (int nt = 0; nt < 4; nt++)
#pragma unroll
            for (int i = 0; i < 4; i++) c[mt][nt][i] = 0.f;

    // staging maps
    const int arow = tid >> 1;                 // 0..127
    const int acol = (tid & 1) * 16;           // 0 or 16
    const int ga = min(row0 + arow, M - 1);    // clamp; stores guarded
    const int brow = tid >> 3;                 // 0..31 (k)
    const int bcol = (tid & 7) * 16;           // 0..112 (n)

    const int g4 = lane >> 2;                  // groupID
    const int t4 = lane & 3;                   // thread-in-group

    for (int k0 = 0; k0 < K; k0 += 32) {
        // ---- stage A (128x32), split hi/lo ----
#pragma unroll
        for (int i = 0; i < 4; i++) {
            float4 v = *(const float4*)&A[(size_t)ga * K + k0 + acol + i * 4];
            uint4 h, l;
            h.x = tf32_rna(v.x); l.x = tf32_rna(v.x - __uint_as_float(h.x));
            h.y = tf32_rna(v.y); l.y = tf32_rna(v.y - __uint_as_float(h.y));
            h.z = tf32_rna(v.z); l.z = tf32_rna(v.z - __uint_as_float(h.z));
            h.w = tf32_rna(v.w); l.w = tf32_rna(v.w - __uint_as_float(h.w));
            *(uint4*)&sm[SM_AH + arow * APAD + acol + i * 4] = h;
            *(uint4*)&sm[SM_AL + arow * APAD + acol + i * 4] = l;
        }
        // ---- stage B (32x128) from W[k][n], split hi/lo ----
#pragma unroll
        for (int i = 0; i < 4; i++) {
            float4 v = *(const float4*)&W[(size_t)(k0 + brow) * N + col0 + bcol + i * 4];
            uint4 h, l;
            h.x = tf32_rna(v.x); l.x = tf32_rna(v.x - __uint_as_float(h.x));
            h.y = tf32_rna(v.y); l.y = tf32_rna(v.y - __uint_as_float(h.y));
            h.z = tf32_rna(v.z); l.z = tf32_rna(v.z - __uint_as_float(h.z));
            h.w = tf32_rna(v.w); l.w = tf32_rna(v.w - __uint_as_float(h.w));
            *(uint4*)&sm[SM_BH + brow * BPAD + bcol + i * 4] = h;
            *(uint4*)&sm[SM_BL + brow * BPAD + bcol + i * 4] = l;
        }
        __syncthreads();

#pragma unroll
        for (int k8 = 0; k8 < 4; k8++) {
            const int kb = k8 * 8;
            uint32_t bh[4][2], bl[4][2];
#pragma unroll
            for (int nt = 0; nt < 4; nt++) {
                const int n = wn + nt * 8 + g4;
                const int kk = kb + t4;
                bh[nt][0] = sm[SM_BH + kk * BPAD + n];
                bh[nt][1] = sm[SM_BH + (kk + 4) * BPAD + n];
                bl[nt][0] = sm[SM_BL + kk * BPAD + n];
                bl[nt][1] = sm[SM_BL + (kk + 4) * BPAD + n];
            }
#pragma unroll
            for (int mt = 0; mt < 4; mt++) {
                const int m = wm + mt * 16 + g4;
                const int kk = kb + t4;
                uint32_t ah[4], al[4];
                ah[0] = sm[SM_AH + m * APAD + kk];
                ah[1] = sm[SM_AH + (m + 8) * APAD + kk];
                ah[2] = sm[SM_AH + m * APAD + kk + 4];
                ah[3] = sm[SM_AH + (m + 8) * APAD + kk + 4];
                al[0] = sm[SM_AL + m * APAD + kk];
                al[1] = sm[SM_AL + (m + 8) * APAD + kk];
                al[2] = sm[SM_AL + m * APAD + kk + 4];
                al[3] = sm[SM_AL + (m + 8) * APAD + kk + 4];
#pragma unroll
                for (int nt = 0; nt < 4; nt++) {
                    MMA_TF32(c[mt][nt], ah, bh[nt]);
                    MMA_TF32(c[mt][nt], ah, bl[nt]);
                    MMA_TF32(c[mt][nt], al, bh[nt]);
                }
            }
        }
        __syncthreads();
    }

    // ---- epilogue: C fragments -> global ----
#pragma unroll
    for (int mt = 0; mt < 4; mt++) {
        const int r = row0 + wm + mt * 16 + g4;
#pragma unroll
        for (int nt = 0; nt < 4; nt++) {
            const int cc = col0 + wn + nt * 8 + t4 * 2;
            if (r < M)
                *(float2*)&C[(size_t)r * N + cc] = make_float2(c[mt][nt][0], c[mt][nt][1]);
            if (r + 8 < M)
                *(float2*)&C[(size_t)(r + 8) * N + cc] = make_float2(c[mt][nt][2], c[mt][nt][3]);
        }
    }
}

// ---------------- small SGEMM (layer 2, N=16): 64x64x16 tile ----------------
#define BM 64
#define BN 64
#define BK 16
__global__ void sgemm_small(const float* __restrict__ B, int M, int N, int K) {
    const float* __restrict__ A = g_bufB;
    float* __restrict__ C = g_bufC;

    __shared__ float As[BK][BM];
    __shared__ float Bs[BK][BN];
    int tid = threadIdx.x;
    int tx = tid & 15, ty = tid >> 4;
    int row0 = blockIdx.y * BM;
    int col0 = blockIdx.x * BN;
    float acc[4][4];
#pragma unroll
    for (int i = 0; i < 4; i++)
#pragma unroll
        for (int j = 0; j < 4; j++) acc[i][j] = 0.f;

    for (int k0 = 0; k0 < K; k0 += BK) {
        for (int i = tid; i < BM * BK; i += 256) {
            int r = i / BK, c = i % BK;
            int gr = row0 + r;
            As[c][r] = (gr < M) ? A[(size_t)gr * K + k0 + c] : 0.f;
        }
        for (int i = tid; i < BK * BN; i += 256) {
            int r = i / BN, c = i % BN;
            int gc = col0 + c;
            Bs[r][c] = (gc < N) ? B[(size_t)(k0 + r) * N + gc] : 0.f;
        }
        __syncthreads();
#pragma unroll
        for (int kk = 0; kk < BK; kk++) {
            float a[4], b[4];
#pragma unroll
            for (int i = 0; i < 4; i++) a[i] = As[kk][ty * 4 + i];
#pragma unroll
            for (int j = 0; j < 4; j++) b[j] = Bs[kk][tx * 4 + j];
#pragma unroll
            for (int i = 0; i < 4; i++)
#pragma unroll
                for (int j = 0; j < 4; j++) acc[i][j] += a[i] * b[j];
        }
        __syncthreads();
    }
#pragma unroll
    for (int i = 0; i < 4; i++) {
        int row = row0 + ty * 4 + i;
        if (row >= M) continue;
#pragma unroll
        for (int j = 0; j < 4; j++) {
            int col = col0 + tx * 4 + j;
            if (col < N) C[(size_t)row * N + col] = acc[i][j];
        }
    }
}

// ---------------- attention dot products: als/ald per (node, head) ----------------
// HS: 0 = g_bufA, 2 = g_bufC
template <int H, int C, int HS>
__global__ void k_attdot(const float* __restrict__ a_s, const float* __restrict__ a_d) {
    const float* __restrict__ hin = (HS == 0) ? (const float*)g_bufA : (const float*)g_bufC;
    int warp = (blockIdx.x * blockDim.x + threadIdx.x) >> 5;
    int lane = threadIdx.x & 31;
    if (warp >= NN * H) return;
    int n = warp / H, h = warp - n * H;
    float s = 0.f, d = 0.f;
    for (int c = lane; c < C; c += 32) {
        float v = hin[(size_t)n * (H * C) + h * C + c];
        s += v * a_s[h * C + c];
        d += v * a_d[h * C + c];
    }
#pragma unroll
    for (int o = 16; o; o >>= 1) {
        s += __shfl_down_sync(0xffffffffu, s, o);
        d += __shfl_down_sync(0xffffffffu, d, o);
    }
    if (lane == 0) { g_als[n * H + h] = s; g_ald[n * H + h] = d; }
}

// ---------------- aggregation: softmax over incoming edges + weighted sum ----------------
// One block per destination node, blockDim = 32*H. Warp w owns head w.
// HS: 0 = g_bufA, 2 = g_bufC.  OS: 1 = g_bufB, -1 = use outext param
template <int H, int C, int DO_ELU, int HS, int OS>
__global__ void k_agg(const float* __restrict__ bias, float* __restrict__ outext) {
    constexpr int HC = H * C;
    const float* __restrict__ hin = (HS == 0) ? (const float*)g_bufA : (const float*)g_bufC;
    float* __restrict__ out = (OS == 1) ? g_bufB : outext;

    int n = blockIdx.x;
    int warp = threadIdx.x >> 5;            // == head
    int lane = threadIdx.x & 31;
    int beg = g_rowptr[n];
    int deg = g_rowptr[n + 1] - beg;

    __shared__ float sinv[H];

    {
        int h = warp;
        float ald_v = g_ald[n * H + h];
        float mx = -1e30f;
        for (int j = lane; j < deg; j += 32) {
            int src = g_csr[beg + j];
            float v = g_als[src * H + h] + ald_v;
            v = v > 0.f ? v : 0.2f * v;
            mx = fmaxf(mx, v);
        }
#pragma unroll
        for (int o = 16; o; o >>= 1) mx = fmaxf(mx, __shfl_xor_sync(0xffffffffu, mx, o));
        float sum = 0.f;
        for (int j = lane; j < deg; j += 32) {
            int src = g_csr[beg + j];
            float v = g_als[src * H + h] + ald_v;
            v = v > 0.f ? v : 0.2f * v;
            float ex = __expf(v - mx);
            g_ex[(beg + j) * H + h] = ex;
            sum += ex;
        }
#pragma unroll
        for (int o = 16; o; o >>= 1) sum += __shfl_xor_sync(0xffffffffu, sum, o);
        if (lane == 0) sinv[h] = 1.f / sum;
    }
    __syncthreads();

    for (int o = threadIdx.x; o < HC; o += 32 * H) {
        int h = o / C;
        float acc = 0.f;
        for (int j = 0; j < deg; j++) {
            int src = g_csr[beg + j];
            acc += g_ex[(beg + j) * H + h] * hin[(size_t)src * HC + o];
        }
        float r = acc * sinv[h] + bias[o];
        if (DO_ELU) r = r > 0.f ? r : expm1f(r);
        out[(size_t)n * HC + o] = r;
    }
}

// ---------------- launch (graph-capture-safe) ----------------
extern "C" void kernel_launch(void* const* d_in, const int* in_sizes, int n_in,
                              void* d_out, int out_size) {
    const float* x   = (const float*)d_in[0];
    const int*   ei  = (const int*)d_in[1];       // int32 edge_index [2, NE]
    const float* W0  = (const float*)d_in[2];
    const float* as0 = (const float*)d_in[3];
    const float* ad0 = (const float*)d_in[4];
    const float* b0  = (const float*)d_in[5];
    const float* W1  = (const float*)d_in[6];
    const float* as1 = (const float*)d_in[7];
    const float* ad1 = (const float*)d_in[8];
    const float* b1  = (const float*)d_in[9];
    const float* W2  = (const float*)d_in[10];
    const float* as2 = (const float*)d_in[11];
    const float* ad2 = (const float*)d_in[12];
    const float* b2  = (const float*)d_in[13];
    float* out = (float*)d_out;

    // Opt-in to >48KB dynamic smem (no allocation; capture-safe)
    cudaFuncSetAttribute(mma_gemm<-1>, cudaFuncAttributeMaxDynamicSharedMemorySize, MMASM);
    cudaFuncSetAttribute(mma_gemm<1>,  cudaFuncAttributeMaxDynamicSharedMemorySize, MMASM);

    // CSR build (per launch; deterministic)
    k_zero_deg<<<(NN + 255) / 256, 256>>>();
    k_hist<<<(ET + 255) / 256, 256>>>(ei);
    k_scan<<<1, 1024>>>();
    k_scatter<<<(ET + 255) / 256, 256>>>(ei);

    dim3 gmm(FH / 128, (NN + 127) / 128);            // 4 x 391
    dim3 g2((NC + BN - 1) / BN, (NN + BM - 1) / BM);

    // layer 0: A = x (ext), C = g_bufA  (K=128)
    mma_gemm<-1><<<gmm, 256, MMASM>>>(x, W0, NN, FH, F0);
    k_attdot<H0, C0, 0><<<(NN * H0 * 32 + 255) / 256, 256>>>(as0, ad0);
    k_agg<H0, C0, 1, 0, 1><<<NN, 32 * H0>>>(b0, nullptr);

    // layer 1: A = g_bufB, C = g_bufA  (K=512)
    mma_gemm<1><<<gmm, 256, MMASM>>>(nullptr, W1, NN, FH, FH);
    k_attdot<H0, C0, 0><<<(NN * H0 * 32 + 255) / 256, 256>>>(as1, ad1);
    k_agg<H0, C0, 1, 0, 1><<<NN, 32 * H0>>>(b1, nullptr);

    // layer 2: A = g_bufB, C = g_bufC (H=1, C=16, no ELU)
    sgemm_small<<<g2, 256>>>(W2, NN, NC, FH);
    k_attdot<1, NC, 2><<<(NN * 32 + 255) / 256, 256>>>(as2, ad2);
    k_agg<1, NC, 0, 2, -1><<<NN, 32>>>(b2, out);
}

// round 10
// speedup vs baseline: 1.2398x; 1.2398x over previous
#include <cuda_runtime.h>
#include <cuda_bf16.h>
#include <math.h>
#include <stdint.h>

#define NN 50000          // nodes
#define NE 400000         // input edges
#define ET 450000         // edges + self loops
#define H0 8
#define C0 64
#define F0 128
#define FH 512            // H0*C0
#define NC 16

// ---------------- device scratch (no allocations allowed) ----------------
__device__ float g_bufA[NN * FH];      // linear GEMM output per layer
__device__ float g_bufB[NN * FH];      // aggregated+activated output
__device__ float g_bufC[NN * NC];      // layer-2 linear output
__device__ float g_als[NN * H0];
__device__ float g_ald[NN * H0];
__device__ float g_ex [ET * H0];       // per-(edge,head) alpha staging
__device__ int   g_deg[NN];
__device__ int   g_rowptr[NN + 1];
__device__ int   g_cursor[NN];
__device__ int   g_csr[ET];            // src node per CSR slot (sorted by dst)

__device__ __forceinline__ int clampi(int v) {
    return v < 0 ? 0 : (v >= NN ? NN - 1 : v);
}

// ---------------- CSR construction (edge_index is INT32: [2, NE]) ----------------
__global__ void k_zero_deg() {
    int i = blockIdx.x * blockDim.x + threadIdx.x;
    if (i < NN) g_deg[i] = 0;
}

__global__ void k_hist(const int* __restrict__ ei) {
    int e = blockIdx.x * blockDim.x + threadIdx.x;
    if (e >= ET) return;
    int d;
    if (e < NE) d = clampi(ei[NE + e]);
    else        d = e - NE;           // self loop
    atomicAdd(&g_deg[d], 1);
}

__global__ void k_scan() {           // single block, 1024 threads, exclusive scan
    __shared__ int s[1024];
    __shared__ int carry;
    int tid = threadIdx.x;
    if (tid == 0) carry = 0;
    __syncthreads();
    for (int base = 0; base < NN; base += 1024) {
        int i = base + tid;
        int v = (i < NN) ? g_deg[i] : 0;
        s[tid] = v;
        __syncthreads();
        for (int off = 1; off < 1024; off <<= 1) {
            int t = (tid >= off) ? s[tid - off] : 0;
            __syncthreads();
            s[tid] += t;
            __syncthreads();
        }
        if (i < NN) {
            int excl = carry + s[tid] - v;
            g_rowptr[i] = excl;
            g_cursor[i] = excl;
        }
        int tot = s[1023];
        __syncthreads();
        if (tid == 0) carry += tot;
        __syncthreads();
    }
    if (tid == 0) g_rowptr[NN] = ET;
}

__global__ void k_scatter(const int* __restrict__ ei) {
    int e = blockIdx.x * blockDim.x + threadIdx.x;
    if (e >= ET) return;
    int srcv, d;
    if (e < NE) { srcv = clampi(ei[e]); d = clampi(ei[NE + e]); }
    else        { srcv = e - NE;        d = e - NE; }
    int p = atomicAdd(&g_cursor[d], 1);
    if (p >= 0 && p < ET) g_csr[p] = srcv;
}

// ================= mma.sync bf16 GEMM (3xBF16 split): C = A(MxK)*W(KxN) =================
// Block 128x128, BK=32, 8 warps (2x4), warp tile 64x32, m16n8k16 fragments.
#define MMA_BF16(d, a, b) \
    asm volatile("mma.sync.aligned.m16n8k16.row.col.f32.bf16.bf16.f32 " \
        "{%0,%1,%2,%3}, {%4,%5,%6,%7}, {%8,%9}, {%0,%1,%2,%3};" \
        : "+f"((d)[0]), "+f"((d)[1]), "+f"((d)[2]), "+f"((d)[3]) \
        : "r"((a)[0]), "r"((a)[1]), "r"((a)[2]), "r"((a)[3]), \
          "r"((b)[0]), "r"((b)[1]))

// split float pair (even k, odd k) into hi/lo bf16x2 packs (low half = even k)
__device__ __forceinline__ void split_pair(float e, float o, uint32_t& hp, uint32_t& lp) {
    __nv_bfloat162 h2 = __floats2bfloat162_rn(e, o);
    float eh = __bfloat162float(h2.x);
    float oh = __bfloat162float(h2.y);
    __nv_bfloat162 l2 = __floats2bfloat162_rn(e - eh, o - oh);
    hp = *(uint32_t*)&h2;
    lp = *(uint32_t*)&l2;
}

#define PSTR 20                       // row stride in uint32 (16 pairs + 4 pad): conflict-free frags
#define SA_H 0
#define SA_L (128 * PSTR)
#define SB_H (2 * 128 * PSTR)
#define SB_L (3 * 128 * PSTR)
#define SMTOT (4 * 128 * PSTR)        // 10240 uint32 = 40KB (static shared)

// ASEL: -1 = Aext param, 1 = g_bufB.  C = g_bufA.  Requires K%32==0, N%128==0.
template <int ASEL>
__global__ void __launch_bounds__(256, 2)
mma_gemm(const float* __restrict__ Aext, const float* __restrict__ W, int M, int N, int K) {
    const float* __restrict__ A = (ASEL == 1) ? (const float*)g_bufB : Aext;
    float* __restrict__ C = g_bufA;

    __shared__ uint32_t sm[SMTOT];

    const int tid = threadIdx.x;
    const int lane = tid & 31;
    const int wid = tid >> 5;
    const int wm = (wid & 1) * 64;      // warp M offset in block tile
    const int wn = (wid >> 1) * 32;     // warp N offset
    const int row0 = blockIdx.y * 128;
    const int col0 = blockIdx.x * 128;

    const int g4 = lane >> 2;           // groupID (row/col within fragment)
    const int t4 = lane & 3;            // thread-in-group (k-pair select)

    float c[4][4][4];
#pragma unroll
    for (int mt = 0; mt < 4; mt++)
#pragma unroll
        for (int nt = 0; nt < 4; nt++)
#pragma unroll
            for (int i = 0; i < 4; i++) c[mt][nt][i] = 0.f;

    // staging maps
    const int sar = tid >> 1;                 // A row 0..127
    const int sak = (tid & 1) * 16;           // A k-offset (floats): 0 or 16
    const int ga = min(row0 + sar, M - 1);    // clamp; stores guarded
    const int sbn = tid & 127;                // B n 0..127
    const int sbkp = (tid >> 7) * 8;          // B k-pair offset: 0 or 8

    for (int k0 = 0; k0 < K; k0 += 32) {
        // ---- stage A (128x32) split hi/lo bf16 pairs ----
        {
            const float* arow = A + (size_t)ga * K + k0 + sak;
#pragma unroll
            for (int i = 0; i < 4; i++) {
                float4 v = *(const float4*)(arow + i * 4);
                uint32_t h0, l0, h1, l1;
                split_pair(v.x, v.y, h0, l0);
                split_pair(v.z, v.w, h1, l1);
                int kp = (sak >> 1) + i * 2;
                sm[SA_H + sar * PSTR + kp] = h0; sm[SA_H + sar * PSTR + kp + 1] = h1;
                sm[SA_L + sar * PSTR + kp] = l0; sm[SA_L + sar * PSTR + kp + 1] = l1;
            }
        }
        // ---- stage B^T (128n x 32k) from W[k][n], split hi/lo ----
        {
#pragma unroll
            for (int i = 0; i < 8; i++) {
                int kk = k0 + (sbkp + i) * 2;
                float e = W[(size_t)kk * N + col0 + sbn];
                float o = W[(size_t)(kk + 1) * N + col0 + sbn];
                uint32_t hp, lp;
                split_pair(e, o, hp, lp);
                sm[SB_H + sbn * PSTR + sbkp + i] = hp;
                sm[SB_L + sbn * PSTR + sbkp + i] = lp;
            }
        }
        __syncthreads();

#pragma unroll
        for (int ks = 0; ks < 2; ks++) {          // two k16 steps per 32-K chunk
            const int kp0 = ks * 8;
            uint32_t bh[4][2], bl[4][2];
#pragma unroll
            for (int nt = 0; nt < 4; nt++) {
                const int n = wn + nt * 8 + g4;
                bh[nt][0] = sm[SB_H + n * PSTR + kp0 + t4];
                bh[nt][1] = sm[SB_H + n * PSTR + kp0 + t4 + 4];
                bl[nt][0] = sm[SB_L + n * PSTR + kp0 + t4];
                bl[nt][1] = sm[SB_L + n * PSTR + kp0 + t4 + 4];
            }
#pragma unroll
            for (int mt = 0; mt < 4; mt++) {
                const int m = wm + mt * 16 + g4;
                uint32_t ah[4], al[4];
                ah[0] = sm[SA_H + m * PSTR + kp0 + t4];
                ah[1] = sm[SA_H + (m + 8) * PSTR + kp0 + t4];
                ah[2] = sm[SA_H + m * PSTR + kp0 + t4 + 4];
                ah[3] = sm[SA_H + (m + 8) * PSTR + kp0 + t4 + 4];
                al[0] = sm[SA_L + m * PSTR + kp0 + t4];
                al[1] = sm[SA_L + (m + 8) * PSTR + kp0 + t4];
                al[2] = sm[SA_L + m * PSTR + kp0 + t4 + 4];
                al[3] = sm[SA_L + (m + 8) * PSTR + kp0 + t4 + 4];
#pragma unroll
                for (int nt = 0; nt < 4; nt++) {
                    MMA_BF16(c[mt][nt], ah, bh[nt]);
                    MMA_BF16(c[mt][nt], ah, bl[nt]);
                    MMA_BF16(c[mt][nt], al, bh[nt]);
                }
            }
        }
        __syncthreads();
    }

    // ---- epilogue: C fragments -> global ----
#pragma unroll
    for (int mt = 0; mt < 4; mt++) {
        const int r = row0 + wm + mt * 16 + g4;
#pragma unroll
        for (int nt = 0; nt < 4; nt++) {
            const int cc = col0 + wn + nt * 8 + t4 * 2;
            if (r < M)
                *(float2*)&C[(size_t)r * N + cc] = make_float2(c[mt][nt][0], c[mt][nt][1]);
            if (r + 8 < M)
                *(float2*)&C[(size_t)(r + 8) * N + cc] = make_float2(c[mt][nt][2], c[mt][nt][3]);
        }
    }
}

// ---------------- small SGEMM (layer 2, N=16): 64x64x16 tile ----------------
#define BM 64
#define BN 64
#define BK 16
__global__ void sgemm_small(const float* __restrict__ B, int M, int N, int K) {
    const float* __restrict__ A = g_bufB;
    float* __restrict__ C = g_bufC;

    __shared__ float As[BK][BM];
    __shared__ float Bs[BK][BN];
    int tid = threadIdx.x;
    int tx = tid & 15, ty = tid >> 4;
    int row0 = blockIdx.y * BM;
    int col0 = blockIdx.x * BN;
    float acc[4][4];
#pragma unroll
    for (int i = 0; i < 4; i++)
#pragma unroll
        for (int j = 0; j < 4; j++) acc[i][j] = 0.f;

    for (int k0 = 0; k0 < K; k0 += BK) {
        for (int i = tid; i < BM * BK; i += 256) {
            int r = i / BK, c = i % BK;
            int gr = row0 + r;
            As[c][r] = (gr < M) ? A[(size_t)gr * K + k0 + c] : 0.f;
        }
        for (int i = tid; i < BK * BN; i += 256) {
            int r = i / BN, c = i % BN;
            int gc = col0 + c;
            Bs[r][c] = (gc < N) ? B[(size_t)(k0 + r) * N + gc] : 0.f;
        }
        __syncthreads();
#pragma unroll
        for (int kk = 0; kk < BK; kk++) {
            float a[4], b[4];
#pragma unroll
            for (int i = 0; i < 4; i++) a[i] = As[kk][ty * 4 + i];
#pragma unroll
            for (int j = 0; j < 4; j++) b[j] = Bs[kk][tx * 4 + j];
#pragma unroll
            for (int i = 0; i < 4; i++)
#pragma unroll
                for (int j = 0; j < 4; j++) acc[i][j] += a[i] * b[j];
        }
        __syncthreads();
    }
#pragma unroll
    for (int i = 0; i < 4; i++) {
        int row = row0 + ty * 4 + i;
        if (row >= M) continue;
#pragma unroll
        for (int j = 0; j < 4; j++) {
            int col = col0 + tx * 4 + j;
            if (col < N) C[(size_t)row * N + col] = acc[i][j];
        }
    }
}

// ---------------- attention dot products: als/ald per (node, head) ----------------
// HS: 0 = g_bufA, 2 = g_bufC
template <int H, int C, int HS>
__global__ void k_attdot(const float* __restrict__ a_s, const float* __restrict__ a_d) {
    const float* __restrict__ hin = (HS == 0) ? (const float*)g_bufA : (const float*)g_bufC;
    int warp = (blockIdx.x * blockDim.x + threadIdx.x) >> 5;
    int lane = threadIdx.x & 31;
    if (warp >= NN * H) return;
    int n = warp / H, h = warp - n * H;
    float s = 0.f, d = 0.f;
    for (int c = lane; c < C; c += 32) {
        float v = hin[(size_t)n * (H * C) + h * C + c];
        s += v * a_s[h * C + c];
        d += v * a_d[h * C + c];
    }
#pragma unroll
    for (int o = 16; o; o >>= 1) {
        s += __shfl_down_sync(0xffffffffu, s, o);
        d += __shfl_down_sync(0xffffffffu, d, o);
    }
    if (lane == 0) { g_als[n * H + h] = s; g_ald[n * H + h] = d; }
}

// ---------------- aggregation: softmax over incoming edges + weighted sum ----------------
// One block per destination node, blockDim = 32*H. Warp w owns head w.
// HS: 0 = g_bufA, 2 = g_bufC.  OS: 1 = g_bufB, -1 = use outext param
template <int H, int C, int DO_ELU, int HS, int OS>
__global__ void k_agg(const float* __restrict__ bias, float* __restrict__ outext) {
    constexpr int HC = H * C;
    const float* __restrict__ hin = (HS == 0) ? (const float*)g_bufA : (const float*)g_bufC;
    float* __restrict__ out = (OS == 1) ? g_bufB : outext;

    int n = blockIdx.x;
    int warp = threadIdx.x >> 5;            // == head
    int lane = threadIdx.x & 31;
    int beg = g_rowptr[n];
    int deg = g_rowptr[n + 1] - beg;

    __shared__ float sinv[H];

    {
        int h = warp;
        float ald_v = g_ald[n * H + h];
        float mx = -1e30f;
        for (int j = lane; j < deg; j += 32) {
            int src = g_csr[beg + j];
            float v = g_als[src * H + h] + ald_v;
            v = v > 0.f ? v : 0.2f * v;
            mx = fmaxf(mx, v);
        }
#pragma unroll
        for (int o = 16; o; o >>= 1) mx = fmaxf(mx, __shfl_xor_sync(0xffffffffu, mx, o));
        float sum = 0.f;
        for (int j = lane; j < deg; j += 32) {
            int src = g_csr[beg + j];
            float v = g_als[src * H + h] + ald_v;
            v = v > 0.f ? v : 0.2f * v;
            float ex = __expf(v - mx);
            g_ex[(beg + j) * H + h] = ex;
            sum += ex;
        }
#pragma unroll
        for (int o = 16; o; o >>= 1) sum += __shfl_xor_sync(0xffffffffu, sum, o);
        if (lane == 0) sinv[h] = 1.f / sum;
    }
    __syncthreads();

    for (int o = threadIdx.x; o < HC; o += 32 * H) {
        int h = o / C;
        float acc = 0.f;
        for (int j = 0; j < deg; j++) {
            int src = g_csr[beg + j];
            acc += g_ex[(beg + j) * H + h] * hin[(size_t)src * HC + o];
        }
        float r = acc * sinv[h] + bias[o];
        if (DO_ELU) r = r > 0.f ? r : expm1f(r);
        out[(size_t)n * HC + o] = r;
    }
}

// ---------------- launch (graph-capture-safe) ----------------
extern "C" void kernel_launch(void* const* d_in, const int* in_sizes, int n_in,
                              void* d_out, int out_size) {
    const float* x   = (const float*)d_in[0];
    const int*   ei  = (const int*)d_in[1];       // int32 edge_index [2, NE]
    const float* W0  = (const float*)d_in[2];
    const float* as0 = (const float*)d_in[3];
    const float* ad0 = (const float*)d_in[4];
    const float* b0  = (const float*)d_in[5];
    const float* W1  = (const float*)d_in[6];
    const float* as1 = (const float*)d_in[7];
    const float* ad1 = (const float*)d_in[8];
    const float* b1  = (const float*)d_in[9];
    const float* W2  = (const float*)d_in[10];
    const float* as2 = (const float*)d_in[11];
    const float* ad2 = (const float*)d_in[12];
    const float* b2  = (const float*)d_in[13];
    float* out = (float*)d_out;

    // CSR build (per launch; deterministic)
    k_zero_deg<<<(NN + 255) / 256, 256>>>();
    k_hist<<<(ET + 255) / 256, 256>>>(ei);
    k_scan<<<1, 1024>>>();
    k_scatter<<<(ET + 255) / 256, 256>>>(ei);

    dim3 gmm(FH / 128, (NN + 127) / 128);            // 4 x 391
    dim3 g2((NC + BN - 1) / BN, (NN + BM - 1) / BM);

    // layer 0: A = x (ext), C = g_bufA  (K=128)
    mma_gemm<-1><<<gmm, 256>>>(x, W0, NN, FH, F0);
    k_attdot<H0, C0, 0><<<(NN * H0 * 32 + 255) / 256, 256>>>(as0, ad0);
    k_agg<H0, C0, 1, 0, 1><<<NN, 32 * H0>>>(b0, nullptr);

    // layer 1: A = g_bufB, C = g_bufA  (K=512)
    mma_gemm<1><<<gmm, 256>>>(nullptr, W1, NN, FH, FH);
    k_attdot<H0, C0, 0><<<(NN * H0 * 32 + 255) / 256, 256>>>(as1, ad1);
    k_agg<H0, C0, 1, 0, 1><<<NN, 32 * H0>>>(b1, nullptr);

    // layer 2: A = g_bufB, C = g_bufC (H=1, C=16, no ELU)
    sgemm_small<<<g2, 256>>>(W2, NN, NC, FH);
    k_attdot<1, NC, 2><<<(NN * 32 + 255) / 256, 256>>>(as2, ad2);
    k_agg<1, NC, 0, 2, -1><<<NN, 32>>>(b2, out);
}

// round 14
// speedup vs baseline: 1.5500x; 1.2503x over previous
#include <cuda_runtime.h>
#include <cuda_bf16.h>
#include <math.h>
#include <stdint.h>

#define NN 50000          // nodes
#define NE 400000         // input edges
#define ET 450000         // edges + self loops
#define H0 8
#define C0 64
#define F0 128
#define FH 512            // H0*C0
#define NC 16
#define CAP 512           // smem edge cap in k_agg8

// ---------------- device scratch (no allocations allowed) ----------------
__device__ float g_bufA[NN * FH];      // linear GEMM output per layer
__device__ float g_bufB[NN * FH];      // aggregated+activated output
__device__ float g_bufC[NN * NC];      // layer-2 linear output
__device__ float g_als[NN * H0];
__device__ float g_ald[NN * H0];
__device__ float g_ex [ET * H0];       // per-(edge,head) alpha staging (fallback only)
__device__ int   g_deg[NN];
__device__ int   g_start[NN];
__device__ int   g_cursor[NN];
__device__ int   g_csr[ET];            // src node per CSR slot (grouped by dst)
__device__ int   g_total;

__device__ __forceinline__ int clampi(int v) {
    return v < 0 ? 0 : (v >= NN ? NN - 1 : v);
}

// ---------------- CSR construction (edge_index is INT32: [2, NE]) ----------------
__global__ void k_zero_deg() {
    int i = blockIdx.x * blockDim.x + threadIdx.x;
    if (i < NN) g_deg[i] = 0;
    if (i == 0) g_total = 0;
}

__global__ void k_hist(const int* __restrict__ ei) {
    int e = blockIdx.x * blockDim.x + threadIdx.x;
    if (e >= ET) return;
    int d;
    if (e < NE) d = clampi(ei[NE + e]);
    else        d = e - NE;           // self loop
    atomicAdd(&g_deg[d], 1);
}

// warp-aggregated offset allocation (replaces serial prefix scan)
__global__ void k_offsets() {
    int i = blockIdx.x * blockDim.x + threadIdx.x;
    int lane = threadIdx.x & 31;
    int d = (i < NN) ? g_deg[i] : 0;
    int incl = d;
#pragma unroll
    for (int off = 1; off < 32; off <<= 1) {
        int t = __shfl_up_sync(0xffffffffu, incl, off);
        if (lane >= off) incl += t;
    }
    int wsum = __shfl_sync(0xffffffffu, incl, 31);
    int base = 0;
    if (lane == 31) base = atomicAdd(&g_total, wsum);
    base = __shfl_sync(0xffffffffu, base, 31);
    if (i < NN) {
        int st = base + incl - d;
        g_start[i] = st;
        g_cursor[i] = st;
    }
}

__global__ void k_scatter(const int* __restrict__ ei) {
    int e = blockIdx.x * blockDim.x + threadIdx.x;
    if (e >= ET) return;
    int srcv, d;
    if (e < NE) { srcv = clampi(ei[e]); d = clampi(ei[NE + e]); }
    else        { srcv = e - NE;        d = e - NE; }
    int p = atomicAdd(&g_cursor[d], 1);
    if (p >= 0 && p < ET) g_csr[p] = srcv;
}

// ================= mma.sync bf16 GEMM (3xBF16 split): C = A(MxK)*W(KxN) =================
#define MMA_BF16(d, a, b) \
    asm volatile("mma.sync.aligned.m16n8k16.row.col.f32.bf16.bf16.f32 " \
        "{%0,%1,%2,%3}, {%4,%5,%6,%7}, {%8,%9}, {%0,%1,%2,%3};" \
        : "+f"((d)[0]), "+f"((d)[1]), "+f"((d)[2]), "+f"((d)[3]) \
        : "r"((a)[0]), "r"((a)[1]), "r"((a)[2]), "r"((a)[3]), \
          "r"((b)[0]), "r"((b)[1]))

__device__ __forceinline__ void split_pair(float e, float o, uint32_t& hp, uint32_t& lp) {
    __nv_bfloat162 h2 = __floats2bfloat162_rn(e, o);
    float eh = __bfloat162float(h2.x);
    float oh = __bfloat162float(h2.y);
    __nv_bfloat162 l2 = __floats2bfloat162_rn(e - eh, o - oh);
    hp = *(uint32_t*)&h2;
    lp = *(uint32_t*)&l2;
}

#define PSTR 20
#define SA_H 0
#define SA_L (128 * PSTR)
#define SB_H (2 * 128 * PSTR)
#define SB_L (3 * 128 * PSTR)
#define SMTOT (4 * 128 * PSTR)        // 40KB static shared

template <int ASEL>
__global__ void __launch_bounds__(256, 2)
mma_gemm(const float* __restrict__ Aext, const float* __restrict__ W, int M, int N, int K) {
    const float* __restrict__ A = (ASEL == 1) ? (const float*)g_bufB : Aext;
    float* __restrict__ C = g_bufA;

    __shared__ uint32_t sm[SMTOT];

    const int tid = threadIdx.x;
    const int lane = tid & 31;
    const int wid = tid >> 5;
    const int wm = (wid & 1) * 64;
    const int wn = (wid >> 1) * 32;
    const int row0 = blockIdx.y * 128;
    const int col0 = blockIdx.x * 128;

    const int g4 = lane >> 2;
    const int t4 = lane & 3;

    float c[4][4][4];
#pragma unroll
    for (int mt = 0; mt < 4; mt++)
#pragma unroll
        for (int nt = 0; nt < 4; nt++)
#pragma unroll
            for (int i = 0; i < 4; i++) c[mt][nt][i] = 0.f;

    const int sar = tid >> 1;
    const int sak = (tid & 1) * 16;
    const int ga = min(row0 + sar, M - 1);
    const int sbn = tid & 127;
    const int sbkp = (tid >> 7) * 8;

    for (int k0 = 0; k0 < K; k0 += 32) {
        {
            const float* arow = A + (size_t)ga * K + k0 + sak;
#pragma unroll
            for (int i = 0; i < 4; i++) {
                float4 v = *(const float4*)(arow + i * 4);
                uint32_t h0, l0, h1, l1;
                split_pair(v.x, v.y, h0, l0);
                split_pair(v.z, v.w, h1, l1);
                int kp = (sak >> 1) + i * 2;
                sm[SA_H + sar * PSTR + kp] = h0; sm[SA_H + sar * PSTR + kp + 1] = h1;
                sm[SA_L + sar * PSTR + kp] = l0; sm[SA_L + sar * PSTR + kp + 1] = l1;
            }
        }
        {
#pragma unroll
            for (int i = 0; i < 8; i++) {
                int kk = k0 + (sbkp + i) * 2;
                float e = W[(size_t)kk * N + col0 + sbn];
                float o = W[(size_t)(kk + 1) * N + col0 + sbn];
                uint32_t hp, lp;
                split_pair(e, o, hp, lp);
                sm[SB_H + sbn * PSTR + sbkp + i] = hp;
                sm[SB_L + sbn * PSTR + sbkp + i] = lp;
            }
        }
        __syncthreads();

#pragma unroll
        for (int ks = 0; ks < 2; ks++) {
            const int kp0 = ks * 8;
            uint32_t bh[4][2], bl[4][2];
#pragma unroll
            for (int nt = 0; nt < 4; nt++) {
                const int n = wn + nt * 8 + g4;
                bh[nt][0] = sm[SB_H + n * PSTR + kp0 + t4];
                bh[nt][1] = sm[SB_H + n * PSTR + kp0 + t4 + 4];
                bl[nt][0] = sm[SB_L + n * PSTR + kp0 + t4];
                bl[nt][1] = sm[SB_L + n * PSTR + kp0 + t4 + 4];
            }
#pragma unroll
            for (int mt = 0; mt < 4; mt++) {
                const int m = wm + mt * 16 + g4;
                uint32_t ah[4], al[4];
                ah[0] = sm[SA_H + m * PSTR + kp0 + t4];
                ah[1] = sm[SA_H + (m + 8) * PSTR + kp0 + t4];
                ah[2] = sm[SA_H + m * PSTR + kp0 + t4 + 4];
                ah[3] = sm[SA_H + (m + 8) * PSTR + kp0 + t4 + 4];
                al[0] = sm[SA_L + m * PSTR + kp0 + t4];
                al[1] = sm[SA_L + (m + 8) * PSTR + kp0 + t4];
                al[2] = sm[SA_L + m * PSTR + kp0 + t4 + 4];
                al[3] = sm[SA_L + (m + 8) * PSTR + kp0 + t4 + 4];
#pragma unroll
                for (int nt = 0; nt < 4; nt++) {
                    MMA_BF16(c[mt][nt], ah, bh[nt]);
                    MMA_BF16(c[mt][nt], ah, bl[nt]);
                    MMA_BF16(c[mt][nt], al, bh[nt]);
                }
            }
        }
        __syncthreads();
    }

#pragma unroll
    for (int mt = 0; mt < 4; mt++) {
        const int r = row0 + wm + mt * 16 + g4;
#pragma unroll
        for (int nt = 0; nt < 4; nt++) {
            const int cc = col0 + wn + nt * 8 + t4 * 2;
            if (r < M)
                *(float2*)&C[(size_t)r * N + cc] = make_float2(c[mt][nt][0], c[mt][nt][1]);
            if (r + 8 < M)
                *(float2*)&C[(size_t)(r + 8) * N + cc] = make_float2(c[mt][nt][2], c[mt][nt][3]);
        }
    }
}

// ---------------- small SGEMM (layer 2, N=16): 64x64x16 tile ----------------
#define BM 64
#define BN 64
#define BK 16
__global__ void sgemm_small(const float* __restrict__ B, int M, int N, int K) {
    const float* __restrict__ A = g_bufB;
    float* __restrict__ C = g_bufC;

    __shared__ float As[BK][BM];
    __shared__ float Bs[BK][BN];
    int tid = threadIdx.x;
    int tx = tid & 15, ty = tid >> 4;
    int row0 = blockIdx.y * BM;
    int col0 = blockIdx.x * BN;
    float acc[4][4];
#pragma unroll
    for (int i = 0; i < 4; i++)
#pragma unroll
        for (int j = 0; j < 4; j++) acc[i][j] = 0.f;

    for (int k0 = 0; k0 < K; k0 += BK) {
        for (int i = tid; i < BM * BK; i += 256) {
            int r = i / BK, c = i % BK;
            int gr = row0 + r;
            As[c][r] = (gr < M) ? A[(size_t)gr * K + k0 + c] : 0.f;
        }
        for (int i = tid; i < BK * BN; i += 256) {
            int r = i / BN, c = i % BN;
            int gc = col0 + c;
            Bs[r][c] = (gc < N) ? B[(size_t)(k0 + r) * N + gc] : 0.f;
        }
        __syncthreads();
#pragma unroll
        for (int kk = 0; kk < BK; kk++) {
            float a[4], b[4];
#pragma unroll
            for (int i = 0; i < 4; i++) a[i] = As[kk][ty * 4 + i];
#pragma unroll
            for (int j = 0; j < 4; j++) b[j] = Bs[kk][tx * 4 + j];
#pragma unroll
            for (int i = 0; i < 4; i++)
#pragma unroll
                for (int j = 0; j < 4; j++) acc[i][j] += a[i] * b[j];
        }
        __syncthreads();
    }
#pragma unroll
    for (int i = 0; i < 4; i++) {
        int row = row0 + ty * 4 + i;
        if (row >= M) continue;
#pragma unroll
        for (int j = 0; j < 4; j++) {
            int col = col0 + tx * 4 + j;
            if (col < N) C[(size_t)row * N + col] = acc[i][j];
        }
    }
}

// ---------------- attention dot products: als/ald per (node, head) ----------------
template <int H, int C, int HS>
__global__ void k_attdot(const float* __restrict__ a_s, const float* __restrict__ a_d) {
    const float* __restrict__ hin = (HS == 0) ? (const float*)g_bufA : (const float*)g_bufC;
    int warp = (blockIdx.x * blockDim.x + threadIdx.x) >> 5;
    int lane = threadIdx.x & 31;
    if (warp >= NN * H) return;
    int n = warp / H, h = warp - n * H;
    float s = 0.f, d = 0.f;
    for (int c = lane; c < C; c += 32) {
        float v = hin[(size_t)n * (H * C) + h * C + c];
        s += v * a_s[h * C + c];
        d += v * a_d[h * C + c];
    }
#pragma unroll
    for (int o = 16; o; o >>= 1) {
        s += __shfl_down_sync(0xffffffffu, s, o);
        d += __shfl_down_sync(0xffffffffu, d, o);
    }
    if (lane == 0) { g_als[n * H + h] = s; g_ald[n * H + h] = d; }
}

// ======== aggregation for H=8, C=64: smem-staged alpha + float4 phase 3 ========
// 128 threads/block; warp w handles heads 2w, 2w+1 in softmax phases.
__global__ void __launch_bounds__(128)
k_agg8(const float* __restrict__ bias) {
    const float* __restrict__ hin = g_bufA;
    float* __restrict__ out = g_bufB;

    const int n = blockIdx.x;
    const int tid = threadIdx.x;
    const int warp = tid >> 5;
    const int lane = tid & 31;
    const int beg = g_start[n];
    const int deg = g_deg[n];

    __shared__ int   s_src[CAP];
    __shared__ float s_ex[CAP][9];       // pad to 9: conflict-free strided access
    __shared__ float sinv[8];

    if (deg <= CAP) {
        for (int j = tid; j < deg; j += 128) s_src[j] = g_csr[beg + j];
        __syncthreads();

        const int h0 = warp * 2;
        float2 ald2 = *(const float2*)&g_ald[n * 8 + h0];
        float mx0 = -1e30f, mx1 = -1e30f;
        for (int j = lane; j < deg; j += 32) {
            float2 a = *(const float2*)&g_als[s_src[j] * 8 + h0];
            float v0 = a.x + ald2.x; v0 = v0 > 0.f ? v0 : 0.2f * v0;
            float v1 = a.y + ald2.y; v1 = v1 > 0.f ? v1 : 0.2f * v1;
            s_ex[j][h0] = v0; s_ex[j][h0 + 1] = v1;
            mx0 = fmaxf(mx0, v0); mx1 = fmaxf(mx1, v1);
        }
#pragma unroll
        for (int o = 16; o; o >>= 1) {
            mx0 = fmaxf(mx0, __shfl_xor_sync(0xffffffffu, mx0, o));
            mx1 = fmaxf(mx1, __shfl_xor_sync(0xffffffffu, mx1, o));
        }
        float s0 = 0.f, s1 = 0.f;
        for (int j = lane; j < deg; j += 32) {
            float e0 = __expf(s_ex[j][h0] - mx0);
            float e1 = __expf(s_ex[j][h0 + 1] - mx1);
            s_ex[j][h0] = e0; s_ex[j][h0 + 1] = e1;
            s0 += e0; s1 += e1;
        }
#pragma unroll
        for (int o = 16; o; o >>= 1) {
            s0 += __shfl_xor_sync(0xffffffffu, s0, o);
            s1 += __shfl_xor_sync(0xffffffffu, s1, o);
        }
        if (lane == 0) { sinv[h0] = 1.f / s0; sinv[h0 + 1] = 1.f / s1; }
        __syncthreads();

        // phase 3: one float4 per thread (128*4 = 512 = HC)
        const int o4 = tid * 4;
        const int h = tid >> 4;
        float4 acc = make_float4(0.f, 0.f, 0.f, 0.f);
        for (int j = 0; j < deg; j++) {
            int src = s_src[j];
            float al = s_ex[j][h];
            float4 v = *(const float4*)&hin[(size_t)src * FH + o4];
            acc.x += al * v.x; acc.y += al * v.y;
            acc.z += al * v.z; acc.w += al * v.w;
        }
        float iv = sinv[h];
        float4 bv = *(const float4*)&bias[o4];
        float4 r;
        r.x = acc.x * iv + bv.x; r.y = acc.y * iv + bv.y;
        r.z = acc.z * iv + bv.z; r.w = acc.w * iv + bv.w;
        r.x = r.x > 0.f ? r.x : expm1f(r.x);
        r.y = r.y > 0.f ? r.y : expm1f(r.y);
        r.z = r.z > 0.f ? r.z : expm1f(r.z);
        r.w = r.w > 0.f ? r.w : expm1f(r.w);
        *(float4*)&out[(size_t)n * FH + o4] = r;
    } else {
        // fallback (deg > CAP): global g_ex path; warp w handles heads w and w+4
        for (int hh = warp; hh < 8; hh += 4) {
            float ald_v = g_ald[n * 8 + hh];
            float mx = -1e30f;
            for (int j = lane; j < deg; j += 32) {
                int src = g_csr[beg + j];
                float v = g_als[src * 8 + hh] + ald_v;
                v = v > 0.f ? v : 0.2f * v;
                mx = fmaxf(mx, v);
            }
#pragma unroll
            for (int o = 16; o; o >>= 1) mx = fmaxf(mx, __shfl_xor_sync(0xffffffffu, mx, o));
            float sum = 0.f;
            for (int j = lane; j < deg; j += 32) {
                int src = g_csr[beg + j];
                float v = g_als[src * 8 + hh] + ald_v;
                v = v > 0.f ? v : 0.2f * v;
                float ex = __expf(v - mx);
                g_ex[(size_t)(beg + j) * 8 + hh] = ex;
                sum += ex;
            }
#pragma unroll
            for (int o = 16; o; o >>= 1) sum += __shfl_xor_sync(0xffffffffu, sum, o);
            if (lane == 0) sinv[hh] = 1.f / sum;
        }
        __syncthreads();
        const int o4 = tid * 4;
        const int h = tid >> 4;
        float4 acc = make_float4(0.f, 0.f, 0.f, 0.f);
        for (int j = 0; j < deg; j++) {
            int src = g_csr[beg + j];
            float al = g_ex[(size_t)(beg + j) * 8 + h];
            float4 v = *(const float4*)&hin[(size_t)src * FH + o4];
            acc.x += al * v.x; acc.y += al * v.y;
            acc.z += al * v.z; acc.w += al * v.w;
        }
        float iv = sinv[h];
        float4 bv = *(const float4*)&bias[o4];
        float4 r;
        r.x = acc.x * iv + bv.x; r.y = acc.y * iv + bv.y;
        r.z = acc.z * iv + bv.z; r.w = acc.w * iv + bv.w;
        r.x = r.x > 0.f ? r.x : expm1f(r.x);
        r.y = r.y > 0.f ? r.y : expm1f(r.y);
        r.z = r.z > 0.f ? r.z : expm1f(r.z);
        r.w = r.w > 0.f ? r.w : expm1f(r.w);
        *(float4*)&out[(size_t)n * FH + o4] = r;
    }
}

// ---------------- layer-2 aggregation (H=1, C=16, no ELU): 32 threads ----------------
__global__ void k_agg_final(const float* __restrict__ bias, float* __restrict__ out) {
    const float* __restrict__ hin = g_bufC;
    int n = blockIdx.x;
    int lane = threadIdx.x;
    int beg = g_start[n];
    int deg = g_deg[n];

    float ald_v = g_ald[n];
    float mx = -1e30f;
    for (int j = lane; j < deg; j += 32) {
        int src = g_csr[beg + j];
        float v = g_als[src] + ald_v;
        v = v > 0.f ? v : 0.2f * v;
        mx = fmaxf(mx, v);
    }
#pragma unroll
    for (int o = 16; o; o >>= 1) mx = fmaxf(mx, __shfl_xor_sync(0xffffffffu, mx, o));
    float sum = 0.f;
    for (int j = lane; j < deg; j += 32) {
        int src = g_csr[beg + j];
        float v = g_als[src] + ald_v;
        v = v > 0.f ? v : 0.2f * v;
        float ex = __expf(v - mx);
        g_ex[(size_t)(beg + j)] = ex;
        sum += ex;
    }
#pragma unroll
    for (int o = 16; o; o >>= 1) sum += __shfl_xor_sync(0xffffffffu, sum, o);
    float sinv = 1.f / __shfl_sync(0xffffffffu, sum, 0);

    for (int o = lane; o < NC; o += 32) {
        float acc = 0.f;
        for (int j = 0; j < deg; j++) {
            int src = g_csr[beg + j];
            acc += g_ex[(size_t)(beg + j)] * hin[(size_t)src * NC + o];
        }
        out[(size_t)n * NC + o] = acc * sinv + bias[o];
    }
}

// ---------------- launch (graph-capture-safe) ----------------
extern "C" void kernel_launch(void* const* d_in, const int* in_sizes, int n_in,
                              void* d_out, int out_size) {
    const float* x   = (const float*)d_in[0];
    const int*   ei  = (const int*)d_in[1];       // int32 edge_index [2, NE]
    const float* W0  = (const float*)d_in[2];
    const float* as0 = (const float*)d_in[3];
    const float* ad0 = (const float*)d_in[4];
    const float* b0  = (const float*)d_in[5];
    const float* W1  = (const float*)d_in[6];
    const float* as1 = (const float*)d_in[7];
    const float* ad1 = (const float*)d_in[8];
    const float* b1  = (const float*)d_in[9];
    const float* W2  = (const float*)d_in[10];
    const float* as2 = (const float*)d_in[11];
    const float* ad2 = (const float*)d_in[12];
    const float* b2  = (const float*)d_in[13];
    float* out = (float*)d_out;

    // CSR build (per launch)
    k_zero_deg<<<(NN + 255) / 256, 256>>>();
    k_hist<<<(ET + 255) / 256, 256>>>(ei);
    k_offsets<<<(NN + 255) / 256, 256>>>();
    k_scatter<<<(ET + 255) / 256, 256>>>(ei);

    dim3 gmm(FH / 128, (NN + 127) / 128);            // 4 x 391
    dim3 g2((NC + BN - 1) / BN, (NN + BM - 1) / BM);

    // layer 0: A = x (ext), C = g_bufA  (K=128)
    mma_gemm<-1><<<gmm, 256>>>(x, W0, NN, FH, F0);
    k_attdot<H0, C0, 0><<<(NN * H0 * 32 + 255) / 256, 256>>>(as0, ad0);
    k_agg8<<<NN, 128>>>(b0);

    // layer 1: A = g_bufB, C = g_bufA  (K=512)
    mma_gemm<1><<<gmm, 256>>>(nullptr, W1, NN, FH, FH);
    k_attdot<H0, C0, 0><<<(NN * H0 * 32 + 255) / 256, 256>>>(as1, ad1);
    k_agg8<<<NN, 128>>>(b1);

    // layer 2: A = g_bufB, C = g_bufC (H=1, C=16, no ELU)
    sgemm_small<<<g2, 256>>>(W2, NN, NC, FH);
    k_attdot<1, NC, 2><<<(NN * 32 + 255) / 256, 256>>>(as2, ad2);
    k_agg_final<<<NN, 32>>>(b2, out);
}

// round 16
// speedup vs baseline: 1.6812x; 1.0846x over previous
#include <cuda_runtime.h>
#include <cuda_bf16.h>
#include <math.h>
#include <stdint.h>

#define NN 50000          // nodes
#define NE 400000         // input edges
#define ET 450000         // edges + self loops
#define H0 8
#define C0 64
#define F0 128
#define FH 512            // H0*C0
#define NC 16
#define CAP 512           // smem edge cap in k_agg8

// ---------------- device scratch (no allocations allowed) ----------------
__device__ float g_bufA[NN * FH];      // linear GEMM output per layer
__device__ float g_bufB[NN * FH];      // aggregated+activated output (fp32, for layer-2 sgemm)
__device__ float g_bufC[NN * NC];      // layer-2 linear output
__device__ float g_als[NN * H0];
__device__ float g_ald[NN * H0];
__device__ float g_ex [ET * H0];       // fallback alpha staging
__device__ int   g_deg[NN];
__device__ int   g_start[NN];
__device__ int   g_cursor[NN];
__device__ int   g_csr[ET];
__device__ int   g_total;
// pre-split bf16 operands
__device__ __nv_bfloat16 g_xh[NN * F0], g_xl[NN * F0];     // x hi/lo
__device__ __nv_bfloat16 g_bh[NN * FH], g_bl[NN * FH];     // layer-0 agg output hi/lo
__device__ __nv_bfloat16 g_w0h[FH * F0], g_w0l[FH * F0];   // W0^T [N=512][K=128]
__device__ __nv_bfloat16 g_w1h[FH * FH], g_w1l[FH * FH];   // W1^T [512][512]

__device__ __forceinline__ int clampi(int v) {
    return v < 0 ? 0 : (v >= NN ? NN - 1 : v);
}
__device__ __forceinline__ uint32_t smem_u32(const void* p) {
    uint32_t a;
    asm("{ .reg .u64 t; cvta.to.shared.u64 t, %1; cvt.u32.u64 %0, t; }" : "=r"(a) : "l"(p));
    return a;
}

// ---------------- CSR construction (edge_index is INT32: [2, NE]) ----------------
__global__ void k_zero_deg() {
    int i = blockIdx.x * blockDim.x + threadIdx.x;
    if (i < NN) g_deg[i] = 0;
    if (i == 0) g_total = 0;
}

__global__ void k_hist(const int* __restrict__ ei) {
    int e = blockIdx.x * blockDim.x + threadIdx.x;
    if (e >= ET) return;
    int d;
    if (e < NE) d = clampi(ei[NE + e]);
    else        d = e - NE;
    atomicAdd(&g_deg[d], 1);
}

__global__ void k_offsets() {
    int i = blockIdx.x * blockDim.x + threadIdx.x;
    int lane = threadIdx.x & 31;
    int d = (i < NN) ? g_deg[i] : 0;
    int incl = d;
#pragma unroll
    for (int off = 1; off < 32; off <<= 1) {
        int t = __shfl_up_sync(0xffffffffu, incl, off);
        if (lane >= off) incl += t;
    }
    int wsum = __shfl_sync(0xffffffffu, incl, 31);
    int base = 0;
    if (lane == 31) base = atomicAdd(&g_total, wsum);
    base = __shfl_sync(0xffffffffu, base, 31);
    if (i < NN) {
        int st = base + incl - d;
        g_start[i] = st;
        g_cursor[i] = st;
    }
}

__global__ void k_scatter(const int* __restrict__ ei) {
    int e = blockIdx.x * blockDim.x + threadIdx.x;
    if (e >= ET) return;
    int srcv, d;
    if (e < NE) { srcv = clampi(ei[e]); d = clampi(ei[NE + e]); }
    else        { srcv = e - NE;        d = e - NE; }
    int p = atomicAdd(&g_cursor[d], 1);
    if (p >= 0 && p < ET) g_csr[p] = srcv;
}

// ---------------- pre-split kernels ----------------
__global__ void k_split_x(const float* __restrict__ x) {
    int i = blockIdx.x * blockDim.x + threadIdx.x;
    if (i >= NN * F0) return;
    float v = x[i];
    __nv_bfloat16 h = __float2bfloat16(v);
    g_xh[i] = h;
    g_xl[i] = __float2bfloat16(v - __bfloat162float(h));
}

// W[K x N] -> Wt hi/lo [N x K]
template <int WHICH>
__global__ void k_split_wt(const float* __restrict__ W, int K, int N) {
    __nv_bfloat16* th = (WHICH == 0) ? g_w0h : g_w1h;
    __nv_bfloat16* tl = (WHICH == 0) ? g_w0l : g_w1l;
    int i = blockIdx.x * blockDim.x + threadIdx.x;
    if (i >= K * N) return;
    int n = i / K, k = i - n * K;
    float w = W[(size_t)k * N + n];
    __nv_bfloat16 h = __float2bfloat16(w);
    th[i] = h;
    tl[i] = __float2bfloat16(w - __bfloat162float(h));
}

// ================= mma.sync bf16 GEMM (3xBF16, pre-split inputs): C = A*W =================
#define MMA_BF16(d, a, b) \
    asm volatile("mma.sync.aligned.m16n8k16.row.col.f32.bf16.bf16.f32 " \
        "{%0,%1,%2,%3}, {%4,%5,%6,%7}, {%8,%9}, {%0,%1,%2,%3};" \
        : "+f"((d)[0]), "+f"((d)[1]), "+f"((d)[2]), "+f"((d)[3]) \
        : "r"((a)[0]), "r"((a)[1]), "r"((a)[2]), "r"((a)[3]), \
          "r"((b)[0]), "r"((b)[1]))
#define CPA16(dst, src) \
    asm volatile("cp.async.ca.shared.global [%0], [%1], 16;" :: "r"(dst), "l"(src))

#define PSTR 20
#define SA_H 0
#define SA_L (128 * PSTR)
#define SB_H (2 * 128 * PSTR)
#define SB_L (3 * 128 * PSTR)
#define SMTOT (4 * 128 * PSTR)        // 40KB static shared

// LAYER 0: A = g_xh/g_xl (K=128), B = g_w0*; LAYER 1: A = g_bh/g_bl (K=512), B = g_w1*
template <int LAYER>
__global__ void __launch_bounds__(256, 2)
mma_gemm2(int M, int N, int K) {
    const __nv_bfloat16* __restrict__ Ah = (LAYER == 0) ? g_xh : g_bh;
    const __nv_bfloat16* __restrict__ Al = (LAYER == 0) ? g_xl : g_bl;
    const __nv_bfloat16* __restrict__ Bh = (LAYER == 0) ? g_w0h : g_w1h;
    const __nv_bfloat16* __restrict__ Bl = (LAYER == 0) ? g_w0l : g_w1l;
    float* __restrict__ C = g_bufA;

    __shared__ uint32_t sm[SMTOT];
    const uint32_t smb = smem_u32(sm);

    const int tid = threadIdx.x;
    const int lane = tid & 31;
    const int wid = tid >> 5;
    const int wm = (wid & 1) * 64;
    const int wn = (wid >> 1) * 32;
    const int row0 = blockIdx.y * 128;
    const int col0 = blockIdx.x * 128;

    const int g4 = lane >> 2;
    const int t4 = lane & 3;

    float c[4][4][4];
#pragma unroll
    for (int mt = 0; mt < 4; mt++)
#pragma unroll
        for (int nt = 0; nt < 4; nt++)
#pragma unroll
            for (int i = 0; i < 4; i++) c[mt][nt][i] = 0.f;

    // staging map: 512 uint4 per matrix-half; thread handles idx = tid, tid+256
    const int sr0 = tid >> 2;                 // 0..63
    const int sr1 = sr0 + 64;                 // 64..127
    const int sp4 = (tid & 3) * 4;            // pair offset 0,4,8,12
    const int ga0 = min(row0 + sr0, M - 1);
    const int ga1 = min(row0 + sr1, M - 1);
    const int gb0 = col0 + sr0;               // Bt row (N index)
    const int gb1 = col0 + sr1;

    for (int k0 = 0; k0 < K; k0 += 32) {
        const int ke = k0 + sp4 * 2;          // bf16 element offset of this uint4
        CPA16(smb + (SA_H + sr0 * PSTR + sp4) * 4, Ah + (size_t)ga0 * K + ke);
        CPA16(smb + (SA_H + sr1 * PSTR + sp4) * 4, Ah + (size_t)ga1 * K + ke);
        CPA16(smb + (SA_L + sr0 * PSTR + sp4) * 4, Al + (size_t)ga0 * K + ke);
        CPA16(smb + (SA_L + sr1 * PSTR + sp4) * 4, Al + (size_t)ga1 * K + ke);
        CPA16(smb + (SB_H + sr0 * PSTR + sp4) * 4, Bh + (size_t)gb0 * K + ke);
        CPA16(smb + (SB_H + sr1 * PSTR + sp4) * 4, Bh + (size_t)gb1 * K + ke);
        CPA16(smb + (SB_L + sr0 * PSTR + sp4) * 4, Bl + (size_t)gb0 * K + ke);
        CPA16(smb + (SB_L + sr1 * PSTR + sp4) * 4, Bl + (size_t)gb1 * K + ke);
        asm volatile("cp.async.commit_group;");
        asm volatile("cp.async.wait_group 0;");
        __syncthreads();

#pragma unroll
        for (int ks = 0; ks < 2; ks++) {
            const int kp0 = ks * 8;
            uint32_t bh[4][2], bl[4][2];
#pragma unroll
            for (int nt = 0; nt < 4; nt++) {
                const int n = wn + nt * 8 + g4;
                bh[nt][0] = sm[SB_H + n * PSTR + kp0 + t4];
                bh[nt][1] = sm[SB_H + n * PSTR + kp0 + t4 + 4];
                bl[nt][0] = sm[SB_L + n * PSTR + kp0 + t4];
                bl[nt][1] = sm[SB_L + n * PSTR + kp0 + t4 + 4];
            }
#pragma unroll
            for (int mt = 0; mt < 4; mt++) {
                const int m = wm + mt * 16 + g4;
                uint32_t ah[4], al[4];
                ah[0] = sm[SA_H + m * PSTR + kp0 + t4];
                ah[1] = sm[SA_H + (m + 8) * PSTR + kp0 + t4];
                ah[2] = sm[SA_H + m * PSTR + kp0 + t4 + 4];
                ah[3] = sm[SA_H + (m + 8) * PSTR + kp0 + t4 + 4];
                al[0] = sm[SA_L + m * PSTR + kp0 + t4];
                al[1] = sm[SA_L + (m + 8) * PSTR + kp0 + t4];
                al[2] = sm[SA_L + m * PSTR + kp0 + t4 + 4];
                al[3] = sm[SA_L + (m + 8) * PSTR + kp0 + t4 + 4];
#pragma unroll
                for (int nt = 0; nt < 4; nt++) {
                    MMA_BF16(c[mt][nt], ah, bh[nt]);
                    MMA_BF16(c[mt][nt], ah, bl[nt]);
                    MMA_BF16(c[mt][nt], al, bh[nt]);
                }
            }
        }
        __syncthreads();
    }

#pragma unroll
    for (int mt = 0; mt < 4; mt++) {
        const int r = row0 + wm + mt * 16 + g4;
#pragma unroll
        for (int nt = 0; nt < 4; nt++) {
            const int cc = col0 + wn + nt * 8 + t4 * 2;
            if (r < M)
                *(float2*)&C[(size_t)r * N + cc] = make_float2(c[mt][nt][0], c[mt][nt][1]);
            if (r + 8 < M)
                *(float2*)&C[(size_t)(r + 8) * N + cc] = make_float2(c[mt][nt][2], c[mt][nt][3]);
        }
    }
}

// ---------------- small SGEMM (layer 2, N=16): 64x64x16 tile ----------------
#define BM 64
#define BN 64
#define BK 16
__global__ void sgemm_small(const float* __restrict__ B, int M, int N, int K) {
    const float* __restrict__ A = g_bufB;
    float* __restrict__ C = g_bufC;

    __shared__ float As[BK][BM];
    __shared__ float Bs[BK][BN];
    int tid = threadIdx.x;
    int tx = tid & 15, ty = tid >> 4;
    int row0 = blockIdx.y * BM;
    int col0 = blockIdx.x * BN;
    float acc[4][4];
#pragma unroll
    for (int i = 0; i < 4; i++)
#pragma unroll
        for (int j = 0; j < 4; j++) acc[i][j] = 0.f;

    for (int k0 = 0; k0 < K; k0 += BK) {
        for (int i = tid; i < BM * BK; i += 256) {
            int r = i / BK, c = i % BK;
            int gr = row0 + r;
            As[c][r] = (gr < M) ? A[(size_t)gr * K + k0 + c] : 0.f;
        }
        for (int i = tid; i < BK * BN; i += 256) {
            int r = i / BN, c = i % BN;
            int gc = col0 + c;
            Bs[r][c] = (gc < N) ? B[(size_t)(k0 + r) * N + gc] : 0.f;
        }
        __syncthreads();
#pragma unroll
        for (int kk = 0; kk < BK; kk++) {
            float a[4], b[4];
#pragma unroll
            for (int i = 0; i < 4; i++) a[i] = As[kk][ty * 4 + i];
#pragma unroll
            for (int j = 0; j < 4; j++) b[j] = Bs[kk][tx * 4 + j];
#pragma unroll
            for (int i = 0; i < 4; i++)
#pragma unroll
                for (int j = 0; j < 4; j++) acc[i][j] += a[i] * b[j];
        }
        __syncthreads();
    }
#pragma unroll
    for (int i = 0; i < 4; i++) {
        int row = row0 + ty * 4 + i;
        if (row >= M) continue;
#pragma unroll
        for (int j = 0; j < 4; j++) {
            int col = col0 + tx * 4 + j;
            if (col < N) C[(size_t)row * N + col] = acc[i][j];
        }
    }
}

// ---------------- attention dot products ----------------
template <int H, int C, int HS>
__global__ void k_attdot(const float* __restrict__ a_s, const float* __restrict__ a_d) {
    const float* __restrict__ hin = (HS == 0) ? (const float*)g_bufA : (const float*)g_bufC;
    int warp = (blockIdx.x * blockDim.x + threadIdx.x) >> 5;
    int lane = threadIdx.x & 31;
    if (warp >= NN * H) return;
    int n = warp / H, h = warp - n * H;
    float s = 0.f, d = 0.f;
    for (int c = lane; c < C; c += 32) {
        float v = hin[(size_t)n * (H * C) + h * C + c];
        s += v * a_s[h * C + c];
        d += v * a_d[h * C + c];
    }
#pragma unroll
    for (int o = 16; o; o >>= 1) {
        s += __shfl_down_sync(0xffffffffu, s, o);
        d += __shfl_down_sync(0xffffffffu, d, o);
    }
    if (lane == 0) { g_als[n * H + h] = s; g_ald[n * H + h] = d; }
}

// ======== aggregation for H=8, C=64 ========
// WRITE_BF16: also emit hi/lo bf16 of the output (feeds next mma_gemm2)
template <int WRITE_BF16>
__global__ void __launch_bounds__(128)
k_agg8(const float* __restrict__ bias) {
    const float* __restrict__ hin = g_bufA;
    float* __restrict__ out = g_bufB;

    const int n = blockIdx.x;
    const int tid = threadIdx.x;
    const int warp = tid >> 5;
    const int lane = tid & 31;
    const int beg = g_start[n];
    const int deg = g_deg[n];

    __shared__ int   s_src[CAP];
    __shared__ float s_ex[CAP][9];
    __shared__ float sinv[8];

    const int o4 = tid * 4;
    const int h = tid >> 4;
    float4 acc = make_float4(0.f, 0.f, 0.f, 0.f);

    if (deg <= CAP) {
        for (int j = tid; j < deg; j += 128) s_src[j] = g_csr[beg + j];
        __syncthreads();

        const int h0 = warp * 2;
        float2 ald2 = *(const float2*)&g_ald[n * 8 + h0];
        float mx0 = -1e30f, mx1 = -1e30f;
        for (int j = lane; j < deg; j += 32) {
            float2 a = *(const float2*)&g_als[s_src[j] * 8 + h0];
            float v0 = a.x + ald2.x; v0 = v0 > 0.f ? v0 : 0.2f * v0;
            float v1 = a.y + ald2.y; v1 = v1 > 0.f ? v1 : 0.2f * v1;
            s_ex[j][h0] = v0; s_ex[j][h0 + 1] = v1;
            mx0 = fmaxf(mx0, v0); mx1 = fmaxf(mx1, v1);
        }
#pragma unroll
        for (int o = 16; o; o >>= 1) {
            mx0 = fmaxf(mx0, __shfl_xor_sync(0xffffffffu, mx0, o));
            mx1 = fmaxf(mx1, __shfl_xor_sync(0xffffffffu, mx1, o));
        }
        float s0 = 0.f, s1 = 0.f;
        for (int j = lane; j < deg; j += 32) {
            float e0 = __expf(s_ex[j][h0] - mx0);
            float e1 = __expf(s_ex[j][h0 + 1] - mx1);
            s_ex[j][h0] = e0; s_ex[j][h0 + 1] = e1;
            s0 += e0; s1 += e1;
        }
#pragma unroll
        for (int o = 16; o; o >>= 1) {
            s0 += __shfl_xor_sync(0xffffffffu, s0, o);
            s1 += __shfl_xor_sync(0xffffffffu, s1, o);
        }
        if (lane == 0) { sinv[h0] = 1.f / s0; sinv[h0 + 1] = 1.f / s1; }
        __syncthreads();

        for (int j = 0; j < deg; j++) {
            int src = s_src[j];
            float al = s_ex[j][h];
            float4 v = *(const float4*)&hin[(size_t)src * FH + o4];
            acc.x += al * v.x; acc.y += al * v.y;
            acc.z += al * v.z; acc.w += al * v.w;
        }
    } else {
        for (int hh = warp; hh < 8; hh += 4) {
            float ald_v = g_ald[n * 8 + hh];
            float mx = -1e30f;
            for (int j = lane; j < deg; j += 32) {
                int src = g_csr[beg + j];
                float v = g_als[src * 8 + hh] + ald_v;
                v = v > 0.f ? v : 0.2f * v;
                mx = fmaxf(mx, v);
            }
#pragma unroll
            for (int o = 16; o; o >>= 1) mx = fmaxf(mx, __shfl_xor_sync(0xffffffffu, mx, o));
            float sum = 0.f;
            for (int j = lane; j < deg; j += 32) {
                int src = g_csr[beg + j];
                float v = g_als[src * 8 + hh] + ald_v;
                v = v > 0.f ? v : 0.2f * v;
                float ex = __expf(v - mx);
                g_ex[(size_t)(beg + j) * 8 + hh] = ex;
                sum += ex;
            }
#pragma unroll
            for (int o = 16; o; o >>= 1) sum += __shfl_xor_sync(0xffffffffu, sum, o);
            if (lane == 0) sinv[hh] = 1.f / sum;
        }
        __syncthreads();
        for (int j = 0; j < deg; j++) {
            int src = g_csr[beg + j];
            float al = g_ex[(size_t)(beg + j) * 8 + h];
            float4 v = *(const float4*)&hin[(size_t)src * FH + o4];
            acc.x += al * v.x; acc.y += al * v.y;
            acc.z += al * v.z; acc.w += al * v.w;
        }
    }

    float iv = sinv[h];
    float4 bv = *(const float4*)&bias[o4];
    float4 r;
    r.x = acc.x * iv + bv.x; r.y = acc.y * iv + bv.y;
    r.z = acc.z * iv + bv.z; r.w = acc.w * iv + bv.w;
    r.x = r.x > 0.f ? r.x : expm1f(r.x);
    r.y = r.y > 0.f ? r.y : expm1f(r.y);
    r.z = r.z > 0.f ? r.z : expm1f(r.z);
    r.w = r.w > 0.f ? r.w : expm1f(r.w);
    *(float4*)&out[(size_t)n * FH + o4] = r;

    if (WRITE_BF16) {
        __nv_bfloat162 h01 = __floats2bfloat162_rn(r.x, r.y);
        __nv_bfloat162 h23 = __floats2bfloat162_rn(r.z, r.w);
        float lx = r.x - __bfloat162float(h01.x);
        float ly = r.y - __bfloat162float(h01.y);
        float lz = r.z - __bfloat162float(h23.x);
        float lw = r.w - __bfloat162float(h23.y);
        __nv_bfloat162 l01 = __floats2bfloat162_rn(lx, ly);
        __nv_bfloat162 l23 = __floats2bfloat162_rn(lz, lw);
        uint2 hv, lv;
        hv.x = *(uint32_t*)&h01; hv.y = *(uint32_t*)&h23;
        lv.x = *(uint32_t*)&l01; lv.y = *(uint32_t*)&l23;
        *(uint2*)(g_bh + (size_t)n * FH + o4) = hv;
        *(uint2*)(g_bl + (size_t)n * FH + o4) = lv;
    }
}

// ---------------- layer-2 aggregation (H=1, C=16, no ELU) ----------------
__global__ void k_agg_final(const float* __restrict__ bias, float* __restrict__ out) {
    const float* __restrict__ hin = g_bufC;
    int n = blockIdx.x;
    int lane = threadIdx.x;
    int beg = g_start[n];
    int deg = g_deg[n];

    float ald_v = g_ald[n];
    float mx = -1e30f;
    for (int j = lane; j < deg; j += 32) {
        int src = g_csr[beg + j];
        float v = g_als[src] + ald_v;
        v = v > 0.f ? v : 0.2f * v;
        mx = fmaxf(mx, v);
    }
#pragma unroll
    for (int o = 16; o; o >>= 1) mx = fmaxf(mx, __shfl_xor_sync(0xffffffffu, mx, o));
    float sum = 0.f;
    for (int j = lane; j < deg; j += 32) {
        int src = g_csr[beg + j];
        float v = g_als[src] + ald_v;
        v = v > 0.f ? v : 0.2f * v;
        float ex = __expf(v - mx);
        g_ex[(size_t)(beg + j)] = ex;
        sum += ex;
    }
#pragma unroll
    for (int o = 16; o; o >>= 1) sum += __shfl_xor_sync(0xffffffffu, sum, o);
    float sinv = 1.f / __shfl_sync(0xffffffffu, sum, 0);

    for (int o = lane; o < NC; o += 32) {
        float acc = 0.f;
        for (int j = 0; j < deg; j++) {
            int src = g_csr[beg + j];
            acc += g_ex[(size_t)(beg + j)] * hin[(size_t)src * NC + o];
        }
        out[(size_t)n * NC + o] = acc * sinv + bias[o];
    }
}

// ---------------- launch (graph-capture-safe) ----------------
extern "C" void kernel_launch(void* const* d_in, const int* in_sizes, int n_in,
                              void* d_out, int out_size) {
    const float* x   = (const float*)d_in[0];
    const int*   ei  = (const int*)d_in[1];
    const float* W0  = (const float*)d_in[2];
    const float* as0 = (const float*)d_in[3];
    const float* ad0 = (const float*)d_in[4];
    const float* b0  = (const float*)d_in[5];
    const float* W1  = (const float*)d_in[6];
    const float* as1 = (const float*)d_in[7];
    const float* ad1 = (const float*)d_in[8];
    const float* b1  = (const float*)d_in[9];
    const float* W2  = (const float*)d_in[10];
    const float* as2 = (const float*)d_in[11];
    const float* ad2 = (const float*)d_in[12];
    const float* b2  = (const float*)d_in[13];
    float* out = (float*)d_out;

    // CSR build + operand pre-splitting
    k_zero_deg<<<(NN + 255) / 256, 256>>>();
    k_hist<<<(ET + 255) / 256, 256>>>(ei);
    k_offsets<<<(NN + 255) / 256, 256>>>();
    k_scatter<<<(ET + 255) / 256, 256>>>(ei);
    k_split_x<<<(NN * F0 + 255) / 256, 256>>>(x);
    k_split_wt<0><<<(F0 * FH + 255) / 256, 256>>>(W0, F0, FH);
    k_split_wt<1><<<(FH * FH + 255) / 256, 256>>>(W1, FH, FH);

    dim3 gmm(FH / 128, (NN + 127) / 128);            // 4 x 391
    dim3 g2((NC + BN - 1) / BN, (NN + BM - 1) / BM);

    // layer 0
    mma_gemm2<0><<<gmm, 256>>>(NN, FH, F0);
    k_attdot<H0, C0, 0><<<(NN * H0 * 32 + 255) / 256, 256>>>(as0, ad0);
    k_agg8<1><<<NN, 128>>>(b0);                      // writes fp32 + bf16 hi/lo

    // layer 1
    mma_gemm2<1><<<gmm, 256>>>(NN, FH, FH);
    k_attdot<H0, C0, 0><<<(NN * H0 * 32 + 255) / 256, 256>>>(as1, ad1);
    k_agg8<0><<<NN, 128>>>(b1);                      // fp32 only (layer 2 is fp32)

    // layer 2
    sgemm_small<<<g2, 256>>>(W2, NN, NC, FH);
    k_attdot<1, NC, 2><<<(NN * 32 + 255) / 256, 256>>>(as2, ad2);
    k_agg_final<<<NN, 32>>>(b2, out);
}